// round 10
// baseline (speedup 1.0000x reference)
#include <cuda_runtime.h>

// Grouped 3-tap width conv with cyclic rolls, fp32. Single kernel node.
// Grid = 16 k-tiles x 7 heights = 112 blocks, 512 threads.
// Warp-autonomous: each warp owns a 32-i slice, stages its own input
// (syncwarp only), streams its own weight chunks via private triple-buffered
// cp.async, computes with zero block barriers until the final reduce.
// FFMA2 pairs over the two groups (o0,o1): input pairs are natural, weights
// broadcast-duplicated in-register.
//
// y[o,k,n,m] = sum_{i,j} f[o,i,m+j] * w[i,k,j],  f[1..7] = width-rolled x row,
// f[0]=f[8]=0 (taps dropped); height roll baked into the final store index.

#define THREADS  512
#define NWARP    16
#define NCHK     4               // weight chunks per warp
#define RPC      8               // i-rows per chunk
#define WROW     400             // padded weight row bytes (96 floats + 16B pad)
#define WBUF     (RPC * WROW)    // 3200 B per buffer
#define NBUF     3

#define OFF_IN   0
#define SZ_IN    (512 * 64)                  // 32768: row i = 8 float2 (f1..f7,pad)
#define OFF_W    SZ_IN
#define SZ_W     (NWARP * NBUF * WBUF)       // 153600
#define OFF_RED  (OFF_W + SZ_W)              // 186368
#define SZ_RED   (32 * 7 * 16 * 8)           // 28672
#define SMEM_TOT (OFF_RED + SZ_RED)          // 215040

typedef unsigned long long ull;

__device__ __forceinline__ ull ffma2(ull a, ull b, ull c)
{
    ull d;
    asm("fma.rn.f32x2 %0, %1, %2, %3;" : "=l"(d) : "l"(a), "l"(b), "l"(c));
    return d;
}
__device__ __forceinline__ ull dup2(float v)
{
    ull d;
    asm("mov.b64 %0, {%1, %1};" : "=l"(d) : "f"(v));
    return d;
}
__device__ __forceinline__ void cp16(unsigned s, const void* g)
{
    asm volatile("cp.async.cg.shared.global [%0], [%1], 16;" :: "r"(s), "l"(g));
}

__global__ __launch_bounds__(THREADS, 1) void conv_warp(const float* __restrict__ x,
                                                        const float* __restrict__ w,
                                                        float* __restrict__ out)
{
    extern __shared__ char sm[];
    const unsigned sb = (unsigned)__cvta_generic_to_shared(sm);
    const int tid  = threadIdx.x, warp = tid >> 5, lane = tid & 31;
    const int kb   = blockIdx.x, n = blockIdx.y, k0 = kb * 32;
    const int iBase = warp * 32;            // warp-private i slice

    // ---- weight cp.async descriptors: lane = (row rw 0..7, quarter sub 0..3) ----
    const int rw = lane >> 2, sub = lane & 3;
    const float* wsrc = w + (iBase + rw) * 1536 + kb * 96 + sub * 24;
    const unsigned wdst = sb + OFF_W + warp * (NBUF * WBUF) + rw * WROW + sub * 96;

#define ISSUEW(c) do { \
        unsigned d_ = wdst + ((c) % NBUF) * WBUF; \
        const float* s_ = wsrc + (c) * (RPC * 1536); \
        cp16(d_,      s_);      cp16(d_ + 16, s_ + 4);  cp16(d_ + 32, s_ + 8); \
        cp16(d_ + 48, s_ + 12); cp16(d_ + 64, s_ + 16); cp16(d_ + 80, s_ + 20); \
        asm volatile("cp.async.commit_group;"); \
    } while (0)

    ISSUEW(0); ISSUEW(1); ISSUEW(2);        // fill the 3-deep private pipeline

    // ---- input staging (warp-private rows), rolls baked in, (x0,x1) pairs ----
    {
        const int r = lane >> 3, j = lane & 7;   // 4 rows x 8 j-slots; j==7 zeroes pad
        if (j < 7) {
            const int u = (j == 6) ? 1 : (j + 2);   // width roll +1
#pragma unroll
            for (int rr = 0; rr < 8; rr++) {
                int i = iBase + rr * 4 + r;
                float v0 = x[i * 49 + n * 7 + j];
                float v1 = x[(512 + i) * 49 + n * 7 + j];
                *reinterpret_cast<float2*>(sm + OFF_IN + i * 64 + (u - 1) * 8) =
                    make_float2(v0, v1);
            }
        } else {
#pragma unroll
            for (int rr = 0; rr < 8; rr++) {
                int i = iBase + rr * 4 + r;
                *reinterpret_cast<float2*>(sm + OFF_IN + i * 64 + 56) =
                    make_float2(0.f, 0.f);
            }
        }
    }
    __syncwarp();

    // ---- mainloop: lane = channel k0+lane; A[m] = (y_o0, y_o1) pairs ----
    ull A[7];
#pragma unroll
    for (int m = 0; m < 7; m++) A[m] = 0ull;

    const char* inP = sm + OFF_IN + iBase * 64;
    const char* wpB = sm + OFF_W + warp * (NBUF * WBUF);

#pragma unroll
    for (int c = 0; c < NCHK; c++) {
        if (c <= 1)      asm volatile("cp.async.wait_group 2;");
        else if (c == 2) asm volatile("cp.async.wait_group 1;");
        else             asm volatile("cp.async.wait_group 0;");
        __syncwarp();

        const char* wp = wpB + (c % NBUF) * WBUF;
#pragma unroll
        for (int t = 0; t < RPC; t++) {
            const char* ib = inP + (c * RPC + t) * 64;          // warp-uniform row
            ulonglong2 L0 = *reinterpret_cast<const ulonglong2*>(ib);        // f1,f2
            ulonglong2 L1 = *reinterpret_cast<const ulonglong2*>(ib + 16);   // f3,f4
            ulonglong2 L2 = *reinterpret_cast<const ulonglong2*>(ib + 32);   // f5,f6
            ulonglong2 L3 = *reinterpret_cast<const ulonglong2*>(ib + 48);   // f7,pad
            const float* wr = reinterpret_cast<const float*>(wp + t * WROW + lane * 12);
            ull W0 = dup2(wr[0]), W1 = dup2(wr[1]), W2 = dup2(wr[2]);
            ull p1 = L0.x, p2 = L0.y, p3 = L1.x, p4 = L1.y;
            ull p5 = L2.x, p6 = L2.y, p7 = L3.x;

            // A[m] += f[m]*W0 + f[m+1]*W1 + f[m+2]*W2  (f0 = f8 = 0 dropped)
            A[0] = ffma2(p1, W1, A[0]); A[0] = ffma2(p2, W2, A[0]);
            A[1] = ffma2(p1, W0, A[1]); A[1] = ffma2(p2, W1, A[1]); A[1] = ffma2(p3, W2, A[1]);
            A[2] = ffma2(p2, W0, A[2]); A[2] = ffma2(p3, W1, A[2]); A[2] = ffma2(p4, W2, A[2]);
            A[3] = ffma2(p3, W0, A[3]); A[3] = ffma2(p4, W1, A[3]); A[3] = ffma2(p5, W2, A[3]);
            A[4] = ffma2(p4, W0, A[4]); A[4] = ffma2(p5, W1, A[4]); A[4] = ffma2(p6, W2, A[4]);
            A[5] = ffma2(p5, W0, A[5]); A[5] = ffma2(p6, W1, A[5]); A[5] = ffma2(p7, W2, A[5]);
            A[6] = ffma2(p6, W0, A[6]); A[6] = ffma2(p7, W1, A[6]);
        }
        if (c == 0) ISSUEW(3);          // buf0 free after computing chunk 0
    }

    // ---- epilogue: per-warp partials -> one barrier -> final sum + rolls ----
    float2* red = reinterpret_cast<float2*>(sm + OFF_RED);
#pragma unroll
    for (int m = 0; m < 7; m++)
        red[(lane * 7 + m) * 16 + warp] = *reinterpret_cast<float2*>(&A[m]);
    __syncthreads();

    if (tid < 224) {                    // (k-local, m)
        int k = tid / 7, m = tid - k * 7;
        const float2* src = &red[(k * 7 + m) * 16];
        float sx = 0.f, sy = 0.f;
#pragma unroll
        for (int is = 0; is < 16; is++) { sx += src[is].x; sy += src[is].y; }
        int nOut = n + 1; if (nOut == 7) nOut = 0;      // height roll +1
        out[(k0 + k) * 49 + nOut * 7 + m]       = sx;   // group 0
        out[(512 + k0 + k) * 49 + nOut * 7 + m] = sy;   // group 1
    }
}

extern "C" void kernel_launch(void* const* d_in, const int* in_sizes, int n_in,
                              void* d_out, int out_size)
{
    const float* x = (const float*)d_in[0];
    const float* w = (const float*)d_in[1];
    float* out = (float*)d_out;

    cudaFuncSetAttribute(conv_warp, cudaFuncAttributeMaxDynamicSharedMemorySize, SMEM_TOT);
    conv_warp<<<dim3(16, 7), THREADS, SMEM_TOT>>>(x, w, out);
}

// round 11
// speedup vs baseline: 1.1379x; 1.1379x over previous
#include <cuda_runtime.h>

// Grouped 3-tap width conv with cyclic rolls, fp32. Single kernel node.
// Grid = 16 k-tiles x 7 heights = 112 blocks, 512 threads.
// Weights staged with cp.async.bulk (UBLKCP: 1 instr per 384B row, mbarrier
// complete_tx) -- kills the LDGSTS issue-cost plateau (12288 x rt8 ~ 25K cyc).
// o-paired f32x2 mainloop (19 FFMA2/i), full-K in registers, one final reduce.
//
// y[o,k,n,m] = sum_{i,j} f[o,i,m+j] * w[i,k,j],  f[1..7] = width-rolled x row,
// f[0]=f[8]=0 (taps dropped); height roll baked into the final store index.

#define THREADS  512
#define NCHK     4                 // weight chunks of 128 rows
#define RPC      128               // rows per chunk
#define WROW     384               // bytes per weight row (96 floats)
#define WBUF     (RPC * WROW)      // 49152 B per buffer

#define OFF_IN   0
#define SZ_IN    (512 * 64)        // 32768: row i = 7 float2 (x0,x1) + 8B pad
#define OFF_W    SZ_IN             // 32768: two weight buffers
#define OFF_MB   (OFF_W + 2 * WBUF)        // 131072: 2 mbarriers
#define OFF_RED  (OFF_MB + 64)             // 131136
#define SZ_RED   (32 * 7 * 16 * 8)         // 28672
#define SMEM_TOT (OFF_RED + SZ_RED)        // 159808

typedef unsigned long long ull;

__device__ __forceinline__ ull ffma2(ull a, ull b, ull c)
{
    ull d;
    asm("fma.rn.f32x2 %0, %1, %2, %3;" : "=l"(d) : "l"(a), "l"(b), "l"(c));
    return d;
}
__device__ __forceinline__ ull dup2(float v)
{
    ull d;
    asm("mov.b64 %0, {%1, %1};" : "=l"(d) : "f"(v));
    return d;
}
__device__ __forceinline__ void bulk384(unsigned dst, const void* src, unsigned mbar)
{
    asm volatile(
        "cp.async.bulk.shared::cluster.global.mbarrier::complete_tx::bytes "
        "[%0], [%1], 384, [%2];"
        :: "r"(dst), "l"(src), "r"(mbar) : "memory");
}
__device__ __forceinline__ void mbar_init(unsigned mbar, unsigned cnt)
{
    asm volatile("mbarrier.init.shared.b64 [%0], %1;" :: "r"(mbar), "r"(cnt) : "memory");
}
__device__ __forceinline__ void mbar_expect(unsigned mbar, unsigned bytes)
{
    asm volatile("mbarrier.arrive.expect_tx.shared.b64 _, [%0], %1;"
                 :: "r"(mbar), "r"(bytes) : "memory");
}
__device__ __forceinline__ void mbar_wait(unsigned mbar, unsigned parity)
{
    asm volatile(
        "{\n\t"
        ".reg .pred P;\n\t"
        "WL_%=:\n\t"
        "mbarrier.try_wait.parity.acquire.cta.shared::cta.b64 P, [%0], %1, 0x989680;\n\t"
        "@P bra.uni WD_%=;\n\t"
        "bra.uni WL_%=;\n\t"
        "WD_%=:\n\t"
        "}"
        :: "r"(mbar), "r"(parity) : "memory");
}

__global__ __launch_bounds__(THREADS, 1) void conv_bulk(const float* __restrict__ x,
                                                        const float* __restrict__ w,
                                                        float* __restrict__ out)
{
    extern __shared__ char sm[];
    const unsigned sb = (unsigned)__cvta_generic_to_shared(sm);
    const int tid = threadIdx.x, warp = tid >> 5, lane = tid & 31;
    const int kb  = blockIdx.x, n = blockIdx.y, k0 = kb * 32;
    const unsigned mb0 = sb + OFF_MB, mb1 = sb + OFF_MB + 8;

    // ---- init mbarriers (arrive count = 128 issuing threads) ----
    if (tid == 0) { mbar_init(mb0, 128); mbar_init(mb1, 128); }
    __syncthreads();

    // ---- issue chunks 0 and 1 (128 bulk rows each, self-paired expect_tx) ----
    if (tid < 128) {
        mbar_expect(mb0, 384);
        bulk384(sb + OFF_W + tid * WROW,
                w + (0 * RPC + tid) * 1536 + kb * 96, mb0);
    } else if (tid < 256) {
        const int t = tid - 128;
        mbar_expect(mb1, 384);
        bulk384(sb + OFF_W + WBUF + t * WROW,
                w + (1 * RPC + t) * 1536 + kb * 96, mb1);
    }

    // ---- input staging: coalesced element walk (14 x LDG.32 per thread) ----
    {
        int r = tid / 7;                 // row index r = o*512 + i  (once)
        int j = tid - r * 7;             // source width position
        const int nbase = n * 7;
#pragma unroll
        for (int k = 0; k < 14; k++) {
            float v = x[r * 49 + nbase + j];
            int u = (j == 6) ? 1 : (j + 2);            // width roll +1
            int o = r >> 9, i = r & 511;
            *reinterpret_cast<float*>(sm + OFF_IN + i * 64 + (u - 1) * 8 + o * 4) = v;
            j += 1; r += 73;
            if (j == 7) { j = 0; r += 1; }
        }
    }

    // ---- compute: lane = channel k0+lane; A[m] = (y_o0, y_o1) pairs ----
    ull A[7];
#pragma unroll
    for (int m = 0; m < 7; m++) A[m] = 0ull;

#pragma unroll 1
    for (int c = 0; c < NCHK; c++) {
        const int b = c & 1;
        mbar_wait(b ? mb1 : mb0, (c >> 1) & 1);
        __syncthreads();                              // input ready too (c=0)

        const char* wp = sm + OFF_W + b * WBUF + warp * 8 * WROW + lane * 12;
        const char* ip = sm + OFF_IN + ((c * RPC + warp * 8) << 6);

#pragma unroll
        for (int t = 0; t < 8; t++) {
            const char* ib = ip + t * 64;             // warp-uniform -> broadcast
            ulonglong2 L0 = *reinterpret_cast<const ulonglong2*>(ib);        // f1,f2
            ulonglong2 L1 = *reinterpret_cast<const ulonglong2*>(ib + 16);   // f3,f4
            ulonglong2 L2 = *reinterpret_cast<const ulonglong2*>(ib + 32);   // f5,f6
            ull        p7 = *reinterpret_cast<const ull*>(ib + 48);          // f7
            const float* wr = reinterpret_cast<const float*>(wp + t * WROW);
            ull W0 = dup2(wr[0]), W1 = dup2(wr[1]), W2 = dup2(wr[2]);
            ull p1 = L0.x, p2 = L0.y, p3 = L1.x, p4 = L1.y, p5 = L2.x, p6 = L2.y;

            // A[m] += f[m]*W0 + f[m+1]*W1 + f[m+2]*W2  (f0 = f8 = 0 dropped)
            A[0] = ffma2(p1, W1, A[0]); A[0] = ffma2(p2, W2, A[0]);
            A[1] = ffma2(p1, W0, A[1]); A[1] = ffma2(p2, W1, A[1]); A[1] = ffma2(p3, W2, A[1]);
            A[2] = ffma2(p2, W0, A[2]); A[2] = ffma2(p3, W1, A[2]); A[2] = ffma2(p4, W2, A[2]);
            A[3] = ffma2(p3, W0, A[3]); A[3] = ffma2(p4, W1, A[3]); A[3] = ffma2(p5, W2, A[3]);
            A[4] = ffma2(p4, W0, A[4]); A[4] = ffma2(p5, W1, A[4]); A[4] = ffma2(p6, W2, A[4]);
            A[5] = ffma2(p5, W0, A[5]); A[5] = ffma2(p6, W1, A[5]); A[5] = ffma2(p7, W2, A[5]);
            A[6] = ffma2(p6, W0, A[6]); A[6] = ffma2(p7, W1, A[6]);
        }

        if (c + 2 < NCHK) {
            __syncthreads();                          // all warps done with buf b
            if (tid < 128) {
                mbar_expect(b ? mb1 : mb0, 384);
                bulk384(sb + OFF_W + b * WBUF + tid * WROW,
                        w + ((c + 2) * RPC + tid) * 1536 + kb * 96,
                        b ? mb1 : mb0);
            }
        }
    }

    // ---- reduce across 16 warps, then store with height roll ----
    float2* red = reinterpret_cast<float2*>(sm + OFF_RED);
#pragma unroll
    for (int m = 0; m < 7; m++)
        red[(lane * 7 + m) * 16 + warp] = *reinterpret_cast<float2*>(&A[m]);
    __syncthreads();

    if (tid < 224) {                                  // (k-local, m)
        int k = tid / 7, m = tid - k * 7;
        const float2* src = &red[(k * 7 + m) * 16];
        float sx = 0.f, sy = 0.f;
#pragma unroll
        for (int is = 0; is < 16; is++) { sx += src[is].x; sy += src[is].y; }
        int nOut = n + 1; if (nOut == 7) nOut = 0;    // height roll +1
        out[(k0 + k) * 49 + nOut * 7 + m]       = sx; // group 0
        out[(512 + k0 + k) * 49 + nOut * 7 + m] = sy; // group 1
    }
}

extern "C" void kernel_launch(void* const* d_in, const int* in_sizes, int n_in,
                              void* d_out, int out_size)
{
    const float* x = (const float*)d_in[0];
    const float* w = (const float*)d_in[1];
    float* out = (float*)d_out;

    cudaFuncSetAttribute(conv_bulk, cudaFuncAttributeMaxDynamicSharedMemorySize, SMEM_TOT);
    conv_bulk<<<dim3(16, 7), THREADS, SMEM_TOT>>>(x, w, out);
}

// round 12
// speedup vs baseline: 1.3005x; 1.1429x over previous
#include <cuda_runtime.h>

// Grouped 3-tap width conv with cyclic rolls, fp32. Single kernel node.
// Grid = 16 k-tiles x 7 heights = 112 blocks, 512 threads.
// Warp-autonomous weight streams: each warp bulk-copies its own 8 rows/chunk
// into a private triple-buffered smem slice with a private mbarrier -> zero
// block-wide syncs in the mainloop. Conflict-free epilogue reduce layout.
//
// y[o,k,n,m] = sum_{i,j} f[o,i,m+j] * w[i,k,j],  f[1..7] = width-rolled x row,
// f[0]=f[8]=0 (taps dropped); height roll baked into the final store index.

#define THREADS  512
#define NCHK     4                 // chunks of 128 rows (8 rows per warp)
#define WROW     384               // bytes per weight row (96 floats)
#define NBUF     3
#define WSLICE   (NBUF * 8 * WROW) // 9216 B per-warp weight slice

#define OFF_IN   0
#define SZ_IN    (512 * 64)        // 32768: input row i = 7 float2 (x0,x1) + pad
#define OFF_W    SZ_IN
#define SZ_W     (16 * WSLICE)     // 147456
#define OFF_MB   (OFF_W + SZ_W)    // 180224: 16 warps x 3 mbarriers
#define OFF_RED  (OFF_MB + 16 * 3 * 8)     // 180608
#define SZ_RED   (16 * 224 * 8)            // 28672
#define SMEM_TOT (OFF_RED + SZ_RED)        // 209280

typedef unsigned long long ull;

__device__ __forceinline__ ull ffma2(ull a, ull b, ull c)
{
    ull d;
    asm("fma.rn.f32x2 %0, %1, %2, %3;" : "=l"(d) : "l"(a), "l"(b), "l"(c));
    return d;
}
__device__ __forceinline__ ull dup2(float v)
{
    ull d;
    asm("mov.b64 %0, {%1, %1};" : "=l"(d) : "f"(v));
    return d;
}
__device__ __forceinline__ void bulk384(unsigned dst, const void* src, unsigned mbar)
{
    asm volatile(
        "cp.async.bulk.shared::cluster.global.mbarrier::complete_tx::bytes "
        "[%0], [%1], 384, [%2];"
        :: "r"(dst), "l"(src), "r"(mbar) : "memory");
}
__device__ __forceinline__ void mbar_init(unsigned mbar, unsigned cnt)
{
    asm volatile("mbarrier.init.shared.b64 [%0], %1;" :: "r"(mbar), "r"(cnt) : "memory");
}
__device__ __forceinline__ void mbar_expect(unsigned mbar, unsigned bytes)
{
    asm volatile("mbarrier.arrive.expect_tx.shared.b64 _, [%0], %1;"
                 :: "r"(mbar), "r"(bytes) : "memory");
}
__device__ __forceinline__ void mbar_wait(unsigned mbar, unsigned parity)
{
    asm volatile(
        "{\n\t"
        ".reg .pred P;\n\t"
        "WL_%=:\n\t"
        "mbarrier.try_wait.parity.acquire.cta.shared::cta.b64 P, [%0], %1, 0x989680;\n\t"
        "@P bra.uni WD_%=;\n\t"
        "bra.uni WL_%=;\n\t"
        "WD_%=:\n\t"
        "}"
        :: "r"(mbar), "r"(parity) : "memory");
}

__global__ __launch_bounds__(THREADS, 1) void conv_wa(const float* __restrict__ x,
                                                      const float* __restrict__ w,
                                                      float* __restrict__ out)
{
    extern __shared__ char sm[];
    const unsigned sb = (unsigned)__cvta_generic_to_shared(sm);
    const int tid = threadIdx.x, warp = tid >> 5, lane = tid & 31;
    const int kb  = blockIdx.x, n = blockIdx.y, k0 = kb * 32;

    // per-warp mbarriers: mb(warp, b)
    const unsigned mbW = sb + OFF_MB + warp * 24;

    // ---- init mbarriers (count 8: lanes 0-7 issue/arrive) ----
    if (tid < 48) mbar_init(sb + OFF_MB + tid * 8, 8);
    __syncthreads();

    // ---- per-warp bulk issue of chunks 0..2 into the private 3-buffer slice ----
    const unsigned wSl = sb + OFF_W + warp * WSLICE;
    if (lane < 8) {
#pragma unroll
        for (int c = 0; c < 3; c++) {
            mbar_expect(mbW + c * 8, 384);
            bulk384(wSl + c * (8 * WROW) + lane * WROW,
                    w + (c * 128 + warp * 8 + lane) * 1536 + kb * 96,
                    mbW + c * 8);
        }
    }

    // ---- input staging: coalesced element walk (14 x LDG.32 per thread) ----
    {
        int r = tid / 7;                 // r = o*512 + i
        int j = tid - r * 7;             // source width position
        const int nbase = n * 7;
#pragma unroll
        for (int k = 0; k < 14; k++) {
            float v = x[r * 49 + nbase + j];
            int u = (j == 6) ? 1 : (j + 2);            // width roll +1
            int o = r >> 9, i = r & 511;
            *reinterpret_cast<float*>(sm + OFF_IN + i * 64 + (u - 1) * 8 + o * 4) = v;
            j += 1; r += 73;
            if (j == 7) { j = 0; r += 1; }
        }
    }
    __syncthreads();                     // input visible to all warps (only block sync)

    // ---- compute: lane = channel k0+lane; A[m] = (y_o0, y_o1) pairs ----
    ull A[7];
#pragma unroll
    for (int m = 0; m < 7; m++) A[m] = 0ull;

#pragma unroll 1
    for (int c = 0; c < NCHK; c++) {
        const int b = (c < 3) ? c : 0;
        mbar_wait(mbW + b * 8, (c < 3) ? 0 : 1);       // warp-private wait

        const char* wp = sm + OFF_W + warp * WSLICE + b * (8 * WROW) + lane * 12;
        const char* ip = sm + OFF_IN + ((c * 128 + warp * 8) << 6);

#pragma unroll
        for (int t = 0; t < 8; t++) {
            const char* ib = ip + t * 64;              // warp-uniform -> broadcast
            ulonglong2 L0 = *reinterpret_cast<const ulonglong2*>(ib);        // f1,f2
            ulonglong2 L1 = *reinterpret_cast<const ulonglong2*>(ib + 16);   // f3,f4
            ulonglong2 L2 = *reinterpret_cast<const ulonglong2*>(ib + 32);   // f5,f6
            ull        p7 = *reinterpret_cast<const ull*>(ib + 48);          // f7
            const float* wr = reinterpret_cast<const float*>(wp + t * WROW);
            ull W0 = dup2(wr[0]), W1 = dup2(wr[1]), W2 = dup2(wr[2]);
            ull p1 = L0.x, p2 = L0.y, p3 = L1.x, p4 = L1.y, p5 = L2.x, p6 = L2.y;

            // A[m] += f[m]*W0 + f[m+1]*W1 + f[m+2]*W2  (f0 = f8 = 0 dropped)
            A[0] = ffma2(p1, W1, A[0]); A[0] = ffma2(p2, W2, A[0]);
            A[1] = ffma2(p1, W0, A[1]); A[1] = ffma2(p2, W1, A[1]); A[1] = ffma2(p3, W2, A[1]);
            A[2] = ffma2(p2, W0, A[2]); A[2] = ffma2(p3, W1, A[2]); A[2] = ffma2(p4, W2, A[2]);
            A[3] = ffma2(p3, W0, A[3]); A[3] = ffma2(p4, W1, A[3]); A[3] = ffma2(p5, W2, A[3]);
            A[4] = ffma2(p4, W0, A[4]); A[4] = ffma2(p5, W1, A[4]); A[4] = ffma2(p6, W2, A[4]);
            A[5] = ffma2(p5, W0, A[5]); A[5] = ffma2(p6, W1, A[5]); A[5] = ffma2(p7, W2, A[5]);
            A[6] = ffma2(p6, W0, A[6]); A[6] = ffma2(p7, W1, A[6]);
        }

        if (c == 0) {                    // recycle buf0 for chunk 3 (warp-local)
            __syncwarp();
            if (lane < 8) {
                mbar_expect(mbW, 384);
                bulk384(wSl + lane * WROW,
                        w + (3 * 128 + warp * 8 + lane) * 1536 + kb * 96,
                        mbW);
            }
        }
    }

    // ---- epilogue: conflict-free reduce layout ----
    // store: red[warp*224 + lane*7 + m]  (lane stride 56B -> 2-way max)
    float2* red = reinterpret_cast<float2*>(sm + OFF_RED);
#pragma unroll
    for (int m = 0; m < 7; m++)
        red[warp * 224 + lane * 7 + m] = *reinterpret_cast<float2*>(&A[m]);
    __syncthreads();

    if (tid < 224) {                     // t = k*7 + m; reads lane-stride 8B
        float sx = 0.f, sy = 0.f;
#pragma unroll
        for (int is = 0; is < 16; is++) {
            float2 v = red[is * 224 + tid];
            sx += v.x; sy += v.y;
        }
        int k = tid / 7, m = tid - k * 7;
        int nOut = n + 1; if (nOut == 7) nOut = 0;     // height roll +1
        out[(k0 + k) * 49 + nOut * 7 + m]       = sx;  // group 0
        out[(512 + k0 + k) * 49 + nOut * 7 + m] = sy;  // group 1
    }
}

extern "C" void kernel_launch(void* const* d_in, const int* in_sizes, int n_in,
                              void* d_out, int out_size)
{
    const float* x = (const float*)d_in[0];
    const float* w = (const float*)d_in[1];
    float* out = (float*)d_out;

    cudaFuncSetAttribute(conv_wa, cudaFuncAttributeMaxDynamicSharedMemorySize, SMEM_TOT);
    conv_wa<<<dim3(16, 7), THREADS, SMEM_TOT>>>(x, w, out);
}